// round 5
// baseline (speedup 1.0000x reference)
#include <cuda_runtime.h>
#include <math.h>
#include <float.h>

// Problem shape (fixed by the reference)
constexpr int B_ = 2;
constexpr int C_ = 16;
constexpr int D_ = 80;
constexpr int H_ = 96;
constexpr int W_ = 96;
constexpr int DHW = D_ * H_ * W_;             // 737280
constexpr int SP  = B_ * DHW;                 // 1474560
constexpr size_t TEN = (size_t)B_ * C_ * DHW; // elements per tensor

// Scratch: pooled fields [pmax_fix, pavg_fix, pmax_move, pavg_move]
__device__ float g_pool[4 * SP];

// ---------------------------------------------------------------------------
// Kernel 1: channel max/avg pooling for both tensors (float4 vectorized)
// ---------------------------------------------------------------------------
__global__ __launch_bounds__(256)
void pool_kernel(const float* __restrict__ fix, const float* __restrict__ mov) {
    int g4 = blockIdx.x * blockDim.x + threadIdx.x;
    constexpr int Q = DHW / 4;
    if (g4 >= SP / 4) return;
    int b  = g4 / Q;
    int s4 = g4 - b * Q;

    const float4* pf = reinterpret_cast<const float4*>(fix) + (size_t)b * C_ * Q + s4;
    const float4* pm = reinterpret_cast<const float4*>(mov) + (size_t)b * C_ * Q + s4;

    float4 mxf = make_float4(-FLT_MAX, -FLT_MAX, -FLT_MAX, -FLT_MAX);
    float4 mxm = mxf;
    float4 smf = make_float4(0.f, 0.f, 0.f, 0.f);
    float4 smm = smf;
#pragma unroll
    for (int c = 0; c < C_; c++) {
        float4 v = pf[(size_t)c * Q];
        mxf.x = fmaxf(mxf.x, v.x); mxf.y = fmaxf(mxf.y, v.y);
        mxf.z = fmaxf(mxf.z, v.z); mxf.w = fmaxf(mxf.w, v.w);
        smf.x += v.x; smf.y += v.y; smf.z += v.z; smf.w += v.w;
        float4 u = pm[(size_t)c * Q];
        mxm.x = fmaxf(mxm.x, u.x); mxm.y = fmaxf(mxm.y, u.y);
        mxm.z = fmaxf(mxm.z, u.z); mxm.w = fmaxf(mxm.w, u.w);
        smm.x += u.x; smm.y += u.y; smm.z += u.z; smm.w += u.w;
    }
    const float inv = 1.f / 16.f;
    smf.x *= inv; smf.y *= inv; smf.z *= inv; smf.w *= inv;
    smm.x *= inv; smm.y *= inv; smm.z *= inv; smm.w *= inv;

    float4* gp = reinterpret_cast<float4*>(g_pool);
    constexpr int SP4 = SP / 4;
    gp[0 * SP4 + g4] = mxf;
    gp[1 * SP4 + g4] = smf;
    gp[2 * SP4 + g4] = mxm;
    gp[3 * SP4 + g4] = smm;
}

// ---------------------------------------------------------------------------
// Kernel 2: 7x7x7 conv (2ch, 2 gates) + sigmoid + cross-gated residual
// Tile: 32(W) x 32(H) x 2(D), 128 threads (8,8,2), per-thread 4W x 4H outputs
// Scalar FFMA (no packing). One pooled field in smem at a time.
// ---------------------------------------------------------------------------
constexpr int TW = 32, TH = 32, TD = 2;
constexpr int HX = TW + 6;   // 38
constexpr int HXS = 40;      // padded row stride (16B alignment)
constexpr int HY = TH + 6;   // 38
constexpr int HZ = TD + 6;   // 8
constexpr int HALO_F = HZ * HY * HXS;              // 12160 floats = 48.64 KB
constexpr int SMEM_BYTES = (HALO_F + 343) * 4;

__global__ void __launch_bounds__(128, 4)
conv_apply_kernel(const float* __restrict__ fix, const float* __restrict__ mov,
                  const float* __restrict__ w_f2m, const float* __restrict__ w_m2f,
                  float* __restrict__ out) {
    extern __shared__ float smem[];
    float* s_h = smem;             // [HZ][HY][HXS]
    float* s_w = smem + HALO_F;    // 343 weights of current field

    const int tx = threadIdx.x;    // 0..7  (4 W outputs each)
    const int ty = threadIdx.y;    // 0..7  (4 H outputs each)
    const int tz = threadIdx.z;    // 0..1
    const int tid = tx + ty * 8 + tz * 64;

    const int x0 = blockIdx.x * TW;
    const int y0 = blockIdx.y * TH;
    const int bz = blockIdx.z;
    const int b  = bz / (D_ / TD);
    const int z0 = (bz - b * (D_ / TD)) * TD;

    float acc0[4][4], acc1[4][4];     // [w][h] for gate0, gate1
#pragma unroll
    for (int w = 0; w < 4; w++)
#pragma unroll
        for (int h = 0; h < 4; h++) { acc0[w][h] = 0.f; acc1[w][h] = 0.f; }

#pragma unroll 1
    for (int gc = 0; gc < 4; gc++) {   // field: gate = gc>>1, channel = gc&1
        const bool gate0 = (gc < 2);

        // ---- halo for this pooled field ----
        const float* src = g_pool + (size_t)gc * SP + (size_t)b * DHW;
        for (int i = tid; i < HZ * HY * HX; i += 128) {
            int dz  = i / (HY * HX);
            int rem = i - dz * (HY * HX);
            int dy  = rem / HX;
            int dx  = rem - dy * HX;
            int gz = z0 + dz - 3, gy = y0 + dy - 3, gx = x0 + dx - 3;
            float v = 0.f;
            if (gz >= 0 && gz < D_ && gy >= 0 && gy < H_ && gx >= 0 && gx < W_)
                v = src[(gz * H_ + gy) * W_ + gx];
            s_h[(dz * HY + dy) * HXS + dx] = v;
        }
        // ---- weights of this (gate, channel) ----
        const float* wsrc = (gate0 ? w_f2m : w_m2f) + (gc & 1) * 343;
        for (int i = tid; i < 343; i += 128) s_w[i] = wsrc[i];
        __syncthreads();

        // ---- conv into tmp (static register indices) ----
        float tmp[4][4];
#pragma unroll
        for (int w = 0; w < 4; w++)
#pragma unroll
            for (int h = 0; h < 4; h++) tmp[w][h] = 0.f;

#pragma unroll 1
        for (int kz = 0; kz < 7; kz++) {
            const float* slab = s_h + ((tz + kz) * HY + ty * 4) * HXS + tx * 4;
            const float* wz   = s_w + kz * 49;
#pragma unroll
            for (int r = 0; r < 10; r++) {
                const float* p = slab + r * HXS;
                float4 a  = *reinterpret_cast<const float4*>(p);
                float4 c4 = *reinterpret_cast<const float4*>(p + 4);
                float2 e  = *reinterpret_cast<const float2*>(p + 8);
                float rv[10] = {a.x, a.y, a.z, a.w,
                                c4.x, c4.y, c4.z, c4.w,
                                e.x, e.y};
#pragma unroll
                for (int h = 0; h < 4; h++) {
                    const int ky = r - h;
                    if (ky >= 0 && ky <= 6) {
#pragma unroll
                        for (int kx = 0; kx < 7; kx++) {
                            float wv = wz[ky * 7 + kx];
#pragma unroll
                            for (int w = 0; w < 4; w++)
                                tmp[w][h] = fmaf(rv[kx + w], wv, tmp[w][h]);
                        }
                    }
                }
            }
        }

        // ---- merge tmp into the right gate accumulator (predicated) ----
#pragma unroll
        for (int w = 0; w < 4; w++)
#pragma unroll
            for (int h = 0; h < 4; h++) {
                if (gate0) acc0[w][h] += tmp[w][h];
                else       acc1[w][h] += tmp[w][h];
            }

        __syncthreads();   // protect smem before next field overwrites
    }

    // ---- sigmoid gates ----
    float gf[4][4], gm[4][4];
#pragma unroll
    for (int w = 0; w < 4; w++)
#pragma unroll
        for (int h = 0; h < 4; h++) {
            gf[w][h] = 1.f / (1.f + __expf(-acc0[w][h]));
            gm[w][h] = 1.f / (1.f + __expf(-acc1[w][h]));
        }

    // ---- apply: fix_out = mov*sa_fix + fix ; move_out = fix*sa_move + mov ----
    const int z  = z0 + tz;
    const int yb = y0 + ty * 4;
    const int x  = x0 + tx * 4;
    const size_t sbase = (size_t)b * C_ * DHW + (size_t)z * H_ * W_ + (size_t)yb * W_ + x;
    float* out_f = out;
    float* out_m = out + TEN;

#pragma unroll 1
    for (int c = 0; c < C_; c++) {
        size_t oc = sbase + (size_t)c * DHW;
#pragma unroll
        for (int h = 0; h < 4; h++) {
            size_t o = oc + (size_t)h * W_;
            float4 f = *reinterpret_cast<const float4*>(fix + o);
            float4 m = *reinterpret_cast<const float4*>(mov + o);
            float4 of, om;
            of.x = fmaf(m.x, gf[0][h], f.x);  om.x = fmaf(f.x, gm[0][h], m.x);
            of.y = fmaf(m.y, gf[1][h], f.y);  om.y = fmaf(f.y, gm[1][h], m.y);
            of.z = fmaf(m.z, gf[2][h], f.z);  om.z = fmaf(f.z, gm[2][h], m.z);
            of.w = fmaf(m.w, gf[3][h], f.w);  om.w = fmaf(f.w, gm[3][h], m.w);
            *reinterpret_cast<float4*>(out_f + o) = of;
            *reinterpret_cast<float4*>(out_m + o) = om;
        }
    }
}

// ---------------------------------------------------------------------------
extern "C" void kernel_launch(void* const* d_in, const int* in_sizes, int n_in,
                              void* d_out, int out_size) {
    const float* fix   = (const float*)d_in[0];
    const float* mov   = (const float*)d_in[1];
    const float* w_f2m = (const float*)d_in[2];
    const float* w_m2f = (const float*)d_in[3];
    float* out = (float*)d_out;

    static bool attr_set = false;
    if (!attr_set) {
        cudaFuncSetAttribute(conv_apply_kernel,
                             cudaFuncAttributeMaxDynamicSharedMemorySize, SMEM_BYTES);
        attr_set = true;
    }

    // Pass 1: pooling
    {
        int threads = 256;
        int blocks = (SP / 4 + threads - 1) / threads;
        pool_kernel<<<blocks, threads>>>(fix, mov);
    }
    // Pass 2: conv + sigmoid + gated residual
    {
        dim3 block(8, 8, 2);
        dim3 grid(W_ / TW, H_ / TH, B_ * (D_ / TD));  // 3 x 3 x 80
        conv_apply_kernel<<<grid, block, SMEM_BYTES>>>(fix, mov, w_f2m, w_m2f, out);
    }
}

// round 6
// speedup vs baseline: 1.1947x; 1.1947x over previous
#include <cuda_runtime.h>
#include <math.h>
#include <float.h>

// Problem shape (fixed by the reference)
constexpr int B_ = 2;
constexpr int C_ = 16;
constexpr int D_ = 80;
constexpr int H_ = 96;
constexpr int W_ = 96;
constexpr int DHW = D_ * H_ * W_;             // 737280
constexpr int SP  = B_ * DHW;                 // 1474560
constexpr size_t TEN = (size_t)B_ * C_ * DHW; // elements per tensor

// Scratch: per gate, interleaved {max, avg} pairs.
// Layout (as float2): [gate][b*DHW + pos]  -> 2 gates * SP float2 = 4*SP floats
__device__ float g_pool[4 * SP];

typedef unsigned long long ull;

__device__ __forceinline__ void unpack2(float& lo, float& hi, ull v) {
    asm("mov.b64 {%0, %1}, %2;" : "=f"(lo), "=f"(hi) : "l"(v));
}
// packed dual-fp32 FMA: d = a*b + d
__device__ __forceinline__ void fma2(ull& d, ull a, ull b) {
    asm("fma.rn.f32x2 %0, %1, %2, %0;" : "+l"(d) : "l"(a), "l"(b));
}

// ---------------------------------------------------------------------------
// Kernel 1: channel max/avg pooling, writes {max,avg} interleaved per gate
// ---------------------------------------------------------------------------
__global__ __launch_bounds__(256)
void pool_kernel(const float* __restrict__ fix, const float* __restrict__ mov) {
    int g4 = blockIdx.x * blockDim.x + threadIdx.x;   // group of 4 positions
    constexpr int Q = DHW / 4;
    if (g4 >= SP / 4) return;
    int b  = g4 / Q;
    int s4 = g4 - b * Q;

    const float4* pf = reinterpret_cast<const float4*>(fix) + (size_t)b * C_ * Q + s4;
    const float4* pm = reinterpret_cast<const float4*>(mov) + (size_t)b * C_ * Q + s4;

    float4 mxf = make_float4(-FLT_MAX, -FLT_MAX, -FLT_MAX, -FLT_MAX);
    float4 mxm = mxf;
    float4 smf = make_float4(0.f, 0.f, 0.f, 0.f);
    float4 smm = smf;
#pragma unroll
    for (int c = 0; c < C_; c++) {
        float4 v = pf[(size_t)c * Q];
        mxf.x = fmaxf(mxf.x, v.x); mxf.y = fmaxf(mxf.y, v.y);
        mxf.z = fmaxf(mxf.z, v.z); mxf.w = fmaxf(mxf.w, v.w);
        smf.x += v.x; smf.y += v.y; smf.z += v.z; smf.w += v.w;
        float4 u = pm[(size_t)c * Q];
        mxm.x = fmaxf(mxm.x, u.x); mxm.y = fmaxf(mxm.y, u.y);
        mxm.z = fmaxf(mxm.z, u.z); mxm.w = fmaxf(mxm.w, u.w);
        smm.x += u.x; smm.y += u.y; smm.z += u.z; smm.w += u.w;
    }
    const float inv = 1.f / 16.f;

    float4* gp = reinterpret_cast<float4*>(g_pool);
    // float4 index for gate g, position block: (g*SP + b*DHW)/2 + 2*s4
    size_t base0 = ((size_t)0 * SP + (size_t)b * DHW) / 2 + 2 * (size_t)s4;
    size_t base1 = ((size_t)1 * SP + (size_t)b * DHW) / 2 + 2 * (size_t)s4;
    gp[base0 + 0] = make_float4(mxf.x, smf.x * inv, mxf.y, smf.y * inv);
    gp[base0 + 1] = make_float4(mxf.z, smf.z * inv, mxf.w, smf.w * inv);
    gp[base1 + 0] = make_float4(mxm.x, smm.x * inv, mxm.y, smm.y * inv);
    gp[base1 + 1] = make_float4(mxm.z, smm.z * inv, mxm.w, smm.w * inv);
}

// ---------------------------------------------------------------------------
// Kernel 2: 7x7x7 conv (channel-paired f32x2) + sigmoid + cross-gated residual
// Tile: 32(W) x 8(H) x 4(D), 128 threads (8,4,4), per-thread 4W x 2H outputs
// ---------------------------------------------------------------------------
constexpr int TW = 32, TH = 8, TD = 4;
constexpr int HXP  = TW + 6;  // 38 halo pairs per row
constexpr int HXSP = 40;      // padded pair stride (16B-aligned rows)
constexpr int HY = TH + 6;    // 14
constexpr int HZ = TD + 6;    // 10
constexpr int HALO_P = HZ * HY * HXSP;               // 5600 float2 = 44.8 KB
constexpr int SMEM_BYTES = HALO_P * 8 + 343 * 8;     // + paired weights

__global__ void __launch_bounds__(128, 4)
conv_apply_kernel(const float* __restrict__ fix, const float* __restrict__ mov,
                  const float* __restrict__ w_f2m, const float* __restrict__ w_m2f,
                  float* __restrict__ out) {
    extern __shared__ float2 smem2[];
    float2* s_h  = smem2;            // [HZ][HY][HXSP] pairs
    ull*    s_w2 = reinterpret_cast<ull*>(smem2 + HALO_P);  // 343 weight pairs

    const int tx = threadIdx.x;      // 0..7  (4 W outputs)
    const int ty = threadIdx.y;      // 0..3  (2 H outputs)
    const int tz = threadIdx.z;      // 0..3
    const int tid = tx + ty * 8 + tz * 32;

    const int x0 = blockIdx.x * TW;
    const int y0 = blockIdx.y * TH;
    const int bz = blockIdx.z;                // 0..39
    const int b  = bz / (D_ / TD);
    const int z0 = (bz - b * (D_ / TD)) * TD;

    float gsum[2][4][2];   // [gate][w][h]

#pragma unroll
    for (int g = 0; g < 2; g++) {
        // ---- halo: interleaved {max,avg} pairs of this gate's pooled field ----
        const float2* src = reinterpret_cast<const float2*>(g_pool)
                          + (size_t)g * SP + (size_t)b * DHW;
        for (int i = tid; i < HZ * HY * HXP; i += 128) {
            int dz  = i / (HY * HXP);
            int rem = i - dz * (HY * HXP);
            int dy  = rem / HXP;
            int dx  = rem - dy * HXP;
            int gz = z0 + dz - 3, gy = y0 + dy - 3, gx = x0 + dx - 3;
            float2 v = make_float2(0.f, 0.f);
            if (gz >= 0 && gz < D_ && gy >= 0 && gy < H_ && gx >= 0 && gx < W_)
                v = src[(gz * H_ + gy) * W_ + gx];
            s_h[(dz * HY + dy) * HXSP + dx] = v;
        }
        // ---- paired weights {w_ch0[k], w_ch1[k]} for this gate ----
        const float* wsrc = (g == 0 ? w_f2m : w_m2f);
        for (int k = tid; k < 343; k += 128) {
            float2 wp = make_float2(wsrc[k], wsrc[343 + k]);
            reinterpret_cast<float2*>(s_w2)[k] = wp;
        }
        __syncthreads();

        // ---- conv with channel-paired FFMA2 ----
        ull pacc[4][2];
#pragma unroll
        for (int w = 0; w < 4; w++)
#pragma unroll
            for (int h = 0; h < 2; h++) pacc[w][h] = 0ull;

        const float2* slab = s_h + ((size_t)tz * HY + ty * 2) * HXSP + tx * 4;
        const ull*    wz   = s_w2;
#pragma unroll 1
        for (int kz = 0; kz < 7; kz++) {
#pragma unroll
            for (int ky = 0; ky < 7; ky++) {
                ull wk[7];
#pragma unroll
                for (int kx = 0; kx < 7; kx++) wk[kx] = wz[ky * 7 + kx];
#pragma unroll
                for (int h = 0; h < 2; h++) {
                    const float2* p = slab + (ky + h) * HXSP;
                    // 10 pairs = 5 x 16B loads, each yields two 64-bit operands
                    ulonglong2 q0 = *reinterpret_cast<const ulonglong2*>(p);
                    ulonglong2 q1 = *reinterpret_cast<const ulonglong2*>(p + 2);
                    ulonglong2 q2 = *reinterpret_cast<const ulonglong2*>(p + 4);
                    ulonglong2 q3 = *reinterpret_cast<const ulonglong2*>(p + 6);
                    ulonglong2 q4 = *reinterpret_cast<const ulonglong2*>(p + 8);
                    ull pk[10] = {q0.x, q0.y, q1.x, q1.y, q2.x,
                                  q2.y, q3.x, q3.y, q4.x, q4.y};
#pragma unroll
                    for (int kx = 0; kx < 7; kx++) {
#pragma unroll
                        for (int w = 0; w < 4; w++)
                            fma2(pacc[w][h], pk[kx + w], wk[kx]);
                    }
                }
            }
            slab += HY * HXSP;
            wz   += 49;
        }

        // ---- reduce channel pair: conv = lo + hi ----
#pragma unroll
        for (int w = 0; w < 4; w++)
#pragma unroll
            for (int h = 0; h < 2; h++) {
                float lo, hi;
                unpack2(lo, hi, pacc[w][h]);
                gsum[g][w][h] = lo + hi;
            }

        __syncthreads();   // protect smem before next gate overwrites
    }

    // ---- sigmoid gates ----
    float gf[4][2], gm[4][2];
#pragma unroll
    for (int w = 0; w < 4; w++)
#pragma unroll
        for (int h = 0; h < 2; h++) {
            gf[w][h] = 1.f / (1.f + __expf(-gsum[0][w][h]));
            gm[w][h] = 1.f / (1.f + __expf(-gsum[1][w][h]));
        }

    // ---- apply: fix_out = mov*sa_fix + fix ; move_out = fix*sa_move + mov ----
    const int z  = z0 + tz;
    const int yb = y0 + ty * 2;
    const int x  = x0 + tx * 4;
    const size_t sbase = (size_t)b * C_ * DHW + (size_t)z * H_ * W_ + (size_t)yb * W_ + x;
    float* out_f = out;
    float* out_m = out + TEN;

#pragma unroll 1
    for (int c = 0; c < C_; c++) {
        size_t oc = sbase + (size_t)c * DHW;
#pragma unroll
        for (int h = 0; h < 2; h++) {
            size_t o = oc + (size_t)h * W_;
            float4 f = *reinterpret_cast<const float4*>(fix + o);
            float4 m = *reinterpret_cast<const float4*>(mov + o);
            float4 of, om;
            of.x = fmaf(m.x, gf[0][h], f.x);  om.x = fmaf(f.x, gm[0][h], m.x);
            of.y = fmaf(m.y, gf[1][h], f.y);  om.y = fmaf(f.y, gm[1][h], m.y);
            of.z = fmaf(m.z, gf[2][h], f.z);  om.z = fmaf(f.z, gm[2][h], m.z);
            of.w = fmaf(m.w, gf[3][h], f.w);  om.w = fmaf(f.w, gm[3][h], m.w);
            *reinterpret_cast<float4*>(out_f + o) = of;
            *reinterpret_cast<float4*>(out_m + o) = om;
        }
    }
}

// ---------------------------------------------------------------------------
extern "C" void kernel_launch(void* const* d_in, const int* in_sizes, int n_in,
                              void* d_out, int out_size) {
    const float* fix   = (const float*)d_in[0];
    const float* mov   = (const float*)d_in[1];
    const float* w_f2m = (const float*)d_in[2];
    const float* w_m2f = (const float*)d_in[3];
    float* out = (float*)d_out;

    static bool attr_set = false;
    if (!attr_set) {
        cudaFuncSetAttribute(conv_apply_kernel,
                             cudaFuncAttributeMaxDynamicSharedMemorySize, SMEM_BYTES);
        attr_set = true;
    }

    // Pass 1: pooling (writes channel-interleaved pairs)
    {
        int threads = 256;
        int blocks = (SP / 4 + threads - 1) / threads;
        pool_kernel<<<blocks, threads>>>(fix, mov);
    }
    // Pass 2: conv + sigmoid + gated residual
    {
        dim3 block(8, 4, 4);
        dim3 grid(W_ / TW, H_ / TH, B_ * (D_ / TD));  // 3 x 12 x 40 = 1440
        conv_apply_kernel<<<grid, block, SMEM_BYTES>>>(fix, mov, w_f2m, w_m2f, out);
    }
}

// round 7
// speedup vs baseline: 1.2927x; 1.0820x over previous
#include <cuda_runtime.h>
#include <math.h>
#include <float.h>

// Problem shape (fixed by the reference)
constexpr int B_ = 2;
constexpr int C_ = 16;
constexpr int D_ = 80;
constexpr int H_ = 96;
constexpr int W_ = 96;
constexpr int DHW = D_ * H_ * W_;             // 737280
constexpr int SP  = B_ * DHW;                 // 1474560
constexpr size_t TEN = (size_t)B_ * C_ * DHW; // elements per tensor

// Scratch: per gate, interleaved {max, avg} pairs.
// Layout (as float2): [gate][b*DHW + pos]
__device__ float g_pool[4 * SP];

typedef unsigned long long ull;

__device__ __forceinline__ void unpack2(float& lo, float& hi, ull v) {
    asm("mov.b64 {%0, %1}, %2;" : "=f"(lo), "=f"(hi) : "l"(v));
}
// packed dual-fp32 FMA: d = a*b + d
__device__ __forceinline__ void fma2(ull& d, ull a, ull b) {
    asm("fma.rn.f32x2 %0, %1, %2, %0;" : "+l"(d) : "l"(a), "l"(b));
}

// ---------------------------------------------------------------------------
// Kernel 1: channel max/avg pooling, writes {max,avg} interleaved per gate
// ---------------------------------------------------------------------------
__global__ __launch_bounds__(256)
void pool_kernel(const float* __restrict__ fix, const float* __restrict__ mov) {
    int g4 = blockIdx.x * blockDim.x + threadIdx.x;   // group of 4 positions
    constexpr int Q = DHW / 4;
    if (g4 >= SP / 4) return;
    int b  = g4 / Q;
    int s4 = g4 - b * Q;

    const float4* pf = reinterpret_cast<const float4*>(fix) + (size_t)b * C_ * Q + s4;
    const float4* pm = reinterpret_cast<const float4*>(mov) + (size_t)b * C_ * Q + s4;

    float4 mxf = make_float4(-FLT_MAX, -FLT_MAX, -FLT_MAX, -FLT_MAX);
    float4 mxm = mxf;
    float4 smf = make_float4(0.f, 0.f, 0.f, 0.f);
    float4 smm = smf;
#pragma unroll
    for (int c = 0; c < C_; c++) {
        float4 v = pf[(size_t)c * Q];
        mxf.x = fmaxf(mxf.x, v.x); mxf.y = fmaxf(mxf.y, v.y);
        mxf.z = fmaxf(mxf.z, v.z); mxf.w = fmaxf(mxf.w, v.w);
        smf.x += v.x; smf.y += v.y; smf.z += v.z; smf.w += v.w;
        float4 u = pm[(size_t)c * Q];
        mxm.x = fmaxf(mxm.x, u.x); mxm.y = fmaxf(mxm.y, u.y);
        mxm.z = fmaxf(mxm.z, u.z); mxm.w = fmaxf(mxm.w, u.w);
        smm.x += u.x; smm.y += u.y; smm.z += u.z; smm.w += u.w;
    }
    const float inv = 1.f / 16.f;

    float4* gp = reinterpret_cast<float4*>(g_pool);
    size_t base0 = ((size_t)0 * SP + (size_t)b * DHW) / 2 + 2 * (size_t)s4;
    size_t base1 = ((size_t)1 * SP + (size_t)b * DHW) / 2 + 2 * (size_t)s4;
    gp[base0 + 0] = make_float4(mxf.x, smf.x * inv, mxf.y, smf.y * inv);
    gp[base0 + 1] = make_float4(mxf.z, smf.z * inv, mxf.w, smf.w * inv);
    gp[base1 + 0] = make_float4(mxm.x, smm.x * inv, mxm.y, smm.y * inv);
    gp[base1 + 1] = make_float4(mxm.z, smm.z * inv, mxm.w, smm.w * inv);
}

// ---------------------------------------------------------------------------
// Kernel 2: 7x7x7 conv (channel-paired f32x2, row-streamed) + sigmoid + apply
// Tile: 32(W) x 16(H) x 4(D), 128 threads (8,4,4), per-thread 4W x 4H x 1D
// ---------------------------------------------------------------------------
constexpr int TW = 32, TH = 16, TD = 4;
constexpr int HXP  = TW + 6;  // 38 halo pairs per row
constexpr int HXSP = 40;      // padded pair stride (16B-aligned rows)
constexpr int HY = TH + 6;    // 22
constexpr int HZ = TD + 6;    // 10
constexpr int HALO_P = HZ * HY * HXSP;            // 8800 float2 = 70.4 KB
constexpr int SMEM_BYTES = HALO_P * 8 + 343 * 8;  // + paired weights

__global__ void __launch_bounds__(128, 3)
conv_apply_kernel(const float* __restrict__ fix, const float* __restrict__ mov,
                  const float* __restrict__ w_f2m, const float* __restrict__ w_m2f,
                  float* __restrict__ out) {
    extern __shared__ float2 smem2[];
    float2* s_h  = smem2;            // [HZ][HY][HXSP] pairs
    ull*    s_w2 = reinterpret_cast<ull*>(smem2 + HALO_P);  // 343 weight pairs

    const int tx = threadIdx.x;      // 0..7  (4 W outputs)
    const int ty = threadIdx.y;      // 0..3  (4 H outputs)
    const int tz = threadIdx.z;      // 0..3  (1 D output)
    const int tid = tx + ty * 8 + tz * 32;

    const int x0 = blockIdx.x * TW;
    const int y0 = blockIdx.y * TH;
    const int bz = blockIdx.z;                // 0..39
    const int b  = bz / (D_ / TD);
    const int z0 = (bz - b * (D_ / TD)) * TD;

    float gsum[2][4][4];   // [gate][w][h]

#pragma unroll
    for (int g = 0; g < 2; g++) {
        // ---- halo: interleaved {max,avg} pairs of this gate's pooled field ----
        const float2* src = reinterpret_cast<const float2*>(g_pool)
                          + (size_t)g * SP + (size_t)b * DHW;
        for (int i = tid; i < HZ * HY * HXP; i += 128) {
            int dz  = i / (HY * HXP);
            int rem = i - dz * (HY * HXP);
            int dy  = rem / HXP;
            int dx  = rem - dy * HXP;
            int gz = z0 + dz - 3, gy = y0 + dy - 3, gx = x0 + dx - 3;
            float2 v = make_float2(0.f, 0.f);
            if (gz >= 0 && gz < D_ && gy >= 0 && gy < H_ && gx >= 0 && gx < W_)
                v = src[(gz * H_ + gy) * W_ + gx];
            s_h[(dz * HY + dy) * HXSP + dx] = v;
        }
        // ---- paired weights {w_ch0[k], w_ch1[k]} for this gate ----
        const float* wsrc = (g == 0 ? w_f2m : w_m2f);
        for (int k = tid; k < 343; k += 128) {
            reinterpret_cast<float2*>(s_w2)[k] = make_float2(wsrc[k], wsrc[343 + k]);
        }
        __syncthreads();

        // ---- conv: stream rows, channel-paired FFMA2 ----
        ull pacc[4][4];   // [w][h]
#pragma unroll
        for (int w = 0; w < 4; w++)
#pragma unroll
            for (int h = 0; h < 4; h++) pacc[w][h] = 0ull;

#pragma unroll 1
        for (int kz = 0; kz < 7; kz++) {
            const float2* plane = s_h + (((size_t)tz + kz) * HY + ty * 4) * HXSP + tx * 4;
            const ull*    wz    = s_w2 + kz * 49;
#pragma unroll
            for (int r = 0; r < 10; r++) {
                const float2* p = plane + r * HXSP;
                ulonglong2 q0 = *reinterpret_cast<const ulonglong2*>(p);
                ulonglong2 q1 = *reinterpret_cast<const ulonglong2*>(p + 2);
                ulonglong2 q2 = *reinterpret_cast<const ulonglong2*>(p + 4);
                ulonglong2 q3 = *reinterpret_cast<const ulonglong2*>(p + 6);
                ulonglong2 q4 = *reinterpret_cast<const ulonglong2*>(p + 8);
                ull pk[10] = {q0.x, q0.y, q1.x, q1.y, q2.x,
                              q2.y, q3.x, q3.y, q4.x, q4.y};
#pragma unroll
                for (int h = 0; h < 4; h++) {
                    const int ky = r - h;
                    if (ky >= 0 && ky <= 6) {
                        const ull* wr = wz + ky * 7;
#pragma unroll
                        for (int kx = 0; kx < 7; kx++) {
                            ull wv = wr[kx];
#pragma unroll
                            for (int w = 0; w < 4; w++)
                                fma2(pacc[w][h], pk[kx + w], wv);
                        }
                    }
                }
            }
        }

        // ---- reduce channel pair: conv = lo + hi ----
#pragma unroll
        for (int w = 0; w < 4; w++)
#pragma unroll
            for (int h = 0; h < 4; h++) {
                float lo, hi;
                unpack2(lo, hi, pacc[w][h]);
                gsum[g][w][h] = lo + hi;
            }

        __syncthreads();   // protect smem before next gate overwrites
    }

    // ---- sigmoid gates ----
    float gf[4][4], gm[4][4];
#pragma unroll
    for (int w = 0; w < 4; w++)
#pragma unroll
        for (int h = 0; h < 4; h++) {
            gf[w][h] = 1.f / (1.f + __expf(-gsum[0][w][h]));
            gm[w][h] = 1.f / (1.f + __expf(-gsum[1][w][h]));
        }

    // ---- apply: fix_out = mov*sa_fix + fix ; move_out = fix*sa_move + mov ----
    const int z  = z0 + tz;
    const int yb = y0 + ty * 4;
    const int x  = x0 + tx * 4;
    const size_t sbase = (size_t)b * C_ * DHW + (size_t)z * H_ * W_ + (size_t)yb * W_ + x;
    float* out_f = out;
    float* out_m = out + TEN;

#pragma unroll 1
    for (int c = 0; c < C_; c++) {
        size_t oc = sbase + (size_t)c * DHW;
#pragma unroll
        for (int h = 0; h < 4; h++) {
            size_t o = oc + (size_t)h * W_;
            float4 f = *reinterpret_cast<const float4*>(fix + o);
            float4 m = *reinterpret_cast<const float4*>(mov + o);
            float4 of, om;
            of.x = fmaf(m.x, gf[0][h], f.x);  om.x = fmaf(f.x, gm[0][h], m.x);
            of.y = fmaf(m.y, gf[1][h], f.y);  om.y = fmaf(f.y, gm[1][h], m.y);
            of.z = fmaf(m.z, gf[2][h], f.z);  om.z = fmaf(f.z, gm[2][h], m.z);
            of.w = fmaf(m.w, gf[3][h], f.w);  om.w = fmaf(f.w, gm[3][h], m.w);
            *reinterpret_cast<float4*>(out_f + o) = of;
            *reinterpret_cast<float4*>(out_m + o) = om;
        }
    }
}

// ---------------------------------------------------------------------------
extern "C" void kernel_launch(void* const* d_in, const int* in_sizes, int n_in,
                              void* d_out, int out_size) {
    const float* fix   = (const float*)d_in[0];
    const float* mov   = (const float*)d_in[1];
    const float* w_f2m = (const float*)d_in[2];
    const float* w_m2f = (const float*)d_in[3];
    float* out = (float*)d_out;

    static bool attr_set = false;
    if (!attr_set) {
        cudaFuncSetAttribute(conv_apply_kernel,
                             cudaFuncAttributeMaxDynamicSharedMemorySize, SMEM_BYTES);
        attr_set = true;
    }

    // Pass 1: pooling (writes channel-interleaved pairs)
    {
        int threads = 256;
        int blocks = (SP / 4 + threads - 1) / threads;
        pool_kernel<<<blocks, threads>>>(fix, mov);
    }
    // Pass 2: conv + sigmoid + gated residual
    {
        dim3 block(8, 4, 4);
        dim3 grid(W_ / TW, H_ / TH, B_ * (D_ / TD));  // 3 x 6 x 40 = 720
        conv_apply_kernel<<<grid, block, SMEM_BYTES>>>(fix, mov, w_f2m, w_m2f, out);
    }
}

// round 8
// speedup vs baseline: 1.2981x; 1.0042x over previous
#include <cuda_runtime.h>
#include <math.h>
#include <float.h>

// Problem shape (fixed by the reference)
constexpr int B_ = 2;
constexpr int C_ = 16;
constexpr int D_ = 80;
constexpr int H_ = 96;
constexpr int W_ = 96;
constexpr int DHW = D_ * H_ * W_;             // 737280
constexpr int SP  = B_ * DHW;                 // 1474560
constexpr size_t TEN = (size_t)B_ * C_ * DHW; // elements per tensor

// Scratch: per gate, interleaved {max, avg} pairs. (float2)[gate][b*DHW + pos]
__device__ float g_pool[4 * SP];

typedef unsigned long long ull;

__device__ __forceinline__ void unpack2(float& lo, float& hi, ull v) {
    asm("mov.b64 {%0, %1}, %2;" : "=f"(lo), "=f"(hi) : "l"(v));
}
// packed dual-fp32 FMA: d = a*b + d
__device__ __forceinline__ void fma2(ull& d, ull a, ull b) {
    asm("fma.rn.f32x2 %0, %1, %2, %0;" : "+l"(d) : "l"(a), "l"(b));
}

// ---------------------------------------------------------------------------
// Kernel 1: channel max/avg pooling, writes {max,avg} interleaved per gate
// ---------------------------------------------------------------------------
__global__ __launch_bounds__(256)
void pool_kernel(const float* __restrict__ fix, const float* __restrict__ mov) {
    int g4 = blockIdx.x * blockDim.x + threadIdx.x;   // group of 4 positions
    constexpr int Q = DHW / 4;
    if (g4 >= SP / 4) return;
    int b  = g4 / Q;
    int s4 = g4 - b * Q;

    const float4* pf = reinterpret_cast<const float4*>(fix) + (size_t)b * C_ * Q + s4;
    const float4* pm = reinterpret_cast<const float4*>(mov) + (size_t)b * C_ * Q + s4;

    float4 mxf = make_float4(-FLT_MAX, -FLT_MAX, -FLT_MAX, -FLT_MAX);
    float4 mxm = mxf;
    float4 smf = make_float4(0.f, 0.f, 0.f, 0.f);
    float4 smm = smf;
#pragma unroll
    for (int c = 0; c < C_; c++) {
        float4 v = pf[(size_t)c * Q];
        mxf.x = fmaxf(mxf.x, v.x); mxf.y = fmaxf(mxf.y, v.y);
        mxf.z = fmaxf(mxf.z, v.z); mxf.w = fmaxf(mxf.w, v.w);
        smf.x += v.x; smf.y += v.y; smf.z += v.z; smf.w += v.w;
        float4 u = pm[(size_t)c * Q];
        mxm.x = fmaxf(mxm.x, u.x); mxm.y = fmaxf(mxm.y, u.y);
        mxm.z = fmaxf(mxm.z, u.z); mxm.w = fmaxf(mxm.w, u.w);
        smm.x += u.x; smm.y += u.y; smm.z += u.z; smm.w += u.w;
    }
    const float inv = 1.f / 16.f;

    float4* gp = reinterpret_cast<float4*>(g_pool);
    size_t base0 = ((size_t)0 * SP + (size_t)b * DHW) / 2 + 2 * (size_t)s4;
    size_t base1 = ((size_t)1 * SP + (size_t)b * DHW) / 2 + 2 * (size_t)s4;
    gp[base0 + 0] = make_float4(mxf.x, smf.x * inv, mxf.y, smf.y * inv);
    gp[base0 + 1] = make_float4(mxf.z, smf.z * inv, mxf.w, smf.w * inv);
    gp[base1 + 0] = make_float4(mxm.x, smm.x * inv, mxm.y, smm.y * inv);
    gp[base1 + 1] = make_float4(mxm.z, smm.z * inv, mxm.w, smm.w * inv);
}

// ---------------------------------------------------------------------------
// Kernel 2: 7x7x7 conv (channel-paired f32x2, row-streamed) + sigmoid + apply
// Tile: 32(W) x 16(H) x 4(D), 128 threads (8,4,4), per-thread 4W x 4H x 1D
// cp.async halo loads, padded/vectorized weight rows
// ---------------------------------------------------------------------------
constexpr int TW = 32, TH = 16, TD = 4;
constexpr int HXP  = TW + 6;  // 38 halo pairs per row
constexpr int HXSP = 40;      // padded pair stride (16B-aligned rows)
constexpr int HY = TH + 6;    // 22
constexpr int HZ = TD + 6;    // 10
constexpr int HALO_P = HZ * HY * HXSP;            // 8800 float2 = 70.4 KB
// weights padded: [7 kz][7 ky][8] ulls
constexpr int W_ULLS = 7 * 7 * 8;                 // 392
constexpr int SMEM_BYTES = HALO_P * 8 + W_ULLS * 8;

__global__ void __launch_bounds__(128, 3)
conv_apply_kernel(const float* __restrict__ fix, const float* __restrict__ mov,
                  const float* __restrict__ w_f2m, const float* __restrict__ w_m2f,
                  float* __restrict__ out) {
    extern __shared__ float2 smem2[];
    float2* s_h  = smem2;            // [HZ][HY][HXSP] pairs
    ull*    s_w2 = reinterpret_cast<ull*>(smem2 + HALO_P);  // padded weight pairs

    const int tx = threadIdx.x;      // 0..7  (4 W outputs)
    const int ty = threadIdx.y;      // 0..3  (4 H outputs)
    const int tz = threadIdx.z;      // 0..3  (1 D output)
    const int tid = tx + ty * 8 + tz * 32;

    const int x0 = blockIdx.x * TW;
    const int y0 = blockIdx.y * TH;
    const int bz = blockIdx.z;                // 0..39
    const int b  = bz / (D_ / TD);
    const int z0 = (bz - b * (D_ / TD)) * TD;

    const unsigned s_h_sa = (unsigned)__cvta_generic_to_shared(s_h);

    float gsum[2][4][4];   // [gate][w][h]

#pragma unroll 1
    for (int g = 0; g < 2; g++) {
        // ---- halo via cp.async (zfill for OOB) ----
        const float2* src = reinterpret_cast<const float2*>(g_pool)
                          + (size_t)g * SP + (size_t)b * DHW;
        for (int i = tid; i < HZ * HY * HXP; i += 128) {
            int dz  = i / (HY * HXP);
            int rem = i - dz * (HY * HXP);
            int dy  = rem / HXP;
            int dx  = rem - dy * HXP;
            int gz = z0 + dz - 3, gy = y0 + dy - 3, gx = x0 + dx - 3;
            bool ok = ((unsigned)gz < (unsigned)D_) &&
                      ((unsigned)gy < (unsigned)H_) &&
                      ((unsigned)gx < (unsigned)W_);
            int off = ok ? ((gz * H_ + gy) * W_ + gx) : 0;
            unsigned sa = s_h_sa + (unsigned)(((dz * HY + dy) * HXSP + dx) * 8);
            int nbytes = ok ? 8 : 0;
            asm volatile("cp.async.ca.shared.global [%0], [%1], 8, %2;"
                         :: "r"(sa), "l"(src + off), "r"(nbytes));
        }
        asm volatile("cp.async.commit_group;" ::: "memory");

        // ---- paired weights into padded layout [kz][ky][8] ----
        const float* wsrc = (g == 0 ? w_f2m : w_m2f);
        for (int k = tid; k < 343; k += 128) {
            int kz  = k / 49;
            int rem = k - kz * 49;
            int ky  = rem / 7;
            int kx  = rem - ky * 7;
            reinterpret_cast<float2*>(s_w2)[kz * 56 + ky * 8 + kx] =
                make_float2(wsrc[k], wsrc[343 + k]);
        }
        asm volatile("cp.async.wait_group 0;" ::: "memory");
        __syncthreads();

        // ---- conv: stream rows, channel-paired FFMA2 ----
        ull pacc[4][4];   // [w][h]
#pragma unroll
        for (int w = 0; w < 4; w++)
#pragma unroll
            for (int h = 0; h < 4; h++) pacc[w][h] = 0ull;

#pragma unroll 1
        for (int kz = 0; kz < 7; kz++) {
            const float2* plane = s_h + (((size_t)tz + kz) * HY + ty * 4) * HXSP + tx * 4;
            const ull*    wz    = s_w2 + kz * 56;
#pragma unroll
            for (int r = 0; r < 10; r++) {
                const float2* p = plane + r * HXSP;
                ulonglong2 q0 = *reinterpret_cast<const ulonglong2*>(p);
                ulonglong2 q1 = *reinterpret_cast<const ulonglong2*>(p + 2);
                ulonglong2 q2 = *reinterpret_cast<const ulonglong2*>(p + 4);
                ulonglong2 q3 = *reinterpret_cast<const ulonglong2*>(p + 6);
                ulonglong2 q4 = *reinterpret_cast<const ulonglong2*>(p + 8);
                ull pk[10] = {q0.x, q0.y, q1.x, q1.y, q2.x,
                              q2.y, q3.x, q3.y, q4.x, q4.y};
#pragma unroll
                for (int h = 0; h < 4; h++) {
                    const int ky = r - h;
                    if (ky >= 0 && ky <= 6) {
                        const ull* wr = wz + ky * 8;          // 16B aligned
                        ulonglong2 a0 = *reinterpret_cast<const ulonglong2*>(wr);
                        ulonglong2 a1 = *reinterpret_cast<const ulonglong2*>(wr + 2);
                        ulonglong2 a2 = *reinterpret_cast<const ulonglong2*>(wr + 4);
                        ull w6 = wr[6];
                        ull wk[7] = {a0.x, a0.y, a1.x, a1.y, a2.x, a2.y, w6};
#pragma unroll
                        for (int kx = 0; kx < 7; kx++) {
                            ull wv = wk[kx];
#pragma unroll
                            for (int w = 0; w < 4; w++)
                                fma2(pacc[w][h], pk[kx + w], wv);
                        }
                    }
                }
            }
        }

        // ---- reduce channel pair: conv = lo + hi ----
#pragma unroll
        for (int w = 0; w < 4; w++)
#pragma unroll
            for (int h = 0; h < 4; h++) {
                float lo, hi;
                unpack2(lo, hi, pacc[w][h]);
                gsum[g][w][h] = lo + hi;
            }

        __syncthreads();   // protect smem before next gate overwrites
    }

    // ---- sigmoid gates ----
    float gf[4][4], gm[4][4];
#pragma unroll
    for (int w = 0; w < 4; w++)
#pragma unroll
        for (int h = 0; h < 4; h++) {
            gf[w][h] = 1.f / (1.f + __expf(-gsum[0][w][h]));
            gm[w][h] = 1.f / (1.f + __expf(-gsum[1][w][h]));
        }

    // ---- apply: fix_out = mov*sa_fix + fix ; move_out = fix*sa_move + mov ----
    const int z  = z0 + tz;
    const int yb = y0 + ty * 4;
    const int x  = x0 + tx * 4;
    const size_t sbase = (size_t)b * C_ * DHW + (size_t)z * H_ * W_ + (size_t)yb * W_ + x;
    float* out_f = out;
    float* out_m = out + TEN;

#pragma unroll 2
    for (int c = 0; c < C_; c++) {
        size_t oc = sbase + (size_t)c * DHW;
#pragma unroll
        for (int h = 0; h < 4; h++) {
            size_t o = oc + (size_t)h * W_;
            float4 f = *reinterpret_cast<const float4*>(fix + o);
            float4 m = *reinterpret_cast<const float4*>(mov + o);
            float4 of, om;
            of.x = fmaf(m.x, gf[0][h], f.x);  om.x = fmaf(f.x, gm[0][h], m.x);
            of.y = fmaf(m.y, gf[1][h], f.y);  om.y = fmaf(f.y, gm[1][h], m.y);
            of.z = fmaf(m.z, gf[2][h], f.z);  om.z = fmaf(f.z, gm[2][h], m.z);
            of.w = fmaf(m.w, gf[3][h], f.w);  om.w = fmaf(f.w, gm[3][h], m.w);
            *reinterpret_cast<float4*>(out_f + o) = of;
            *reinterpret_cast<float4*>(out_m + o) = om;
        }
    }
}

// ---------------------------------------------------------------------------
extern "C" void kernel_launch(void* const* d_in, const int* in_sizes, int n_in,
                              void* d_out, int out_size) {
    const float* fix   = (const float*)d_in[0];
    const float* mov   = (const float*)d_in[1];
    const float* w_f2m = (const float*)d_in[2];
    const float* w_m2f = (const float*)d_in[3];
    float* out = (float*)d_out;

    static bool attr_set = false;
    if (!attr_set) {
        cudaFuncSetAttribute(conv_apply_kernel,
                             cudaFuncAttributeMaxDynamicSharedMemorySize, SMEM_BYTES);
        attr_set = true;
    }

    // Pass 1: pooling (writes channel-interleaved pairs)
    {
        int threads = 256;
        int blocks = (SP / 4 + threads - 1) / threads;
        pool_kernel<<<blocks, threads>>>(fix, mov);
    }
    // Pass 2: conv + sigmoid + gated residual
    {
        dim3 block(8, 4, 4);
        dim3 grid(W_ / TW, H_ / TH, B_ * (D_ / TD));  // 3 x 6 x 40 = 720
        conv_apply_kernel<<<grid, block, SMEM_BYTES>>>(fix, mov, w_f2m, w_m2f, out);
    }
}